// round 12
// baseline (speedup 1.0000x reference)
#include <cuda_runtime.h>
#include <cuda_fp16.h>
#include <cstdint>
#include <cstddef>

#define B_ 64
#define S_ 2048
#define H_ 512

// ---------------- scratch (no allocations allowed) ----------------
__device__ float g_q[B_ * H_];            // query projection [B,H]
__device__ float g_ep[2][B_ * S_];        // energy partials per n-half
__device__ float g_energy[B_ * S_];       // exp(energy) weights (0 when masked)
__device__ float g_invden[B_];
__device__ __half g_w1tF[H_ * H_];        // W1^T fp16 [n][k]
__device__ __half g_encF[(size_t)B_ * S_ * H_];  // enc fp16

// ---------------- helpers ----------------
__device__ __forceinline__ uint32_t smem_u32(const void* p) {
    uint32_t a;
    asm("{ .reg .u64 t; cvta.to.shared.u64 t, %1; cvt.u32.u64 %0, t; }" : "=r"(a) : "l"(p));
    return a;
}
#define SW128(o) ((o) ^ (((o) >> 3) & 0x70))

__device__ __forceinline__ uint32_t cvtf2(float lo, float hi) {  // f16x2 {hi,lo}
    uint32_t r;
    asm("cvt.rn.f16x2.f32 %0, %1, %2;" : "=r"(r) : "f"(hi), "f"(lo));
    return r;
}
__device__ __forceinline__ float tanh_fast(float x) {
    float e = __expf(2.0f * x);
    return 1.0f - __fdividef(2.0f, e + 1.0f);
}
__device__ __forceinline__ void cp16(uint32_t dst, const void* src) {
    asm volatile("cp.async.cg.shared.global [%0], [%1], 16;" :: "r"(dst), "l"(src) : "memory");
}
__device__ __forceinline__ void cp_commit() {
    asm volatile("cp.async.commit_group;" ::: "memory");
}
__device__ __forceinline__ void cp_wait0() {
    asm volatile("cp.async.wait_group 0;" ::: "memory");
}
__device__ __forceinline__ void ldmx4(uint32_t* r, uint32_t addr) {
    asm volatile("ldmatrix.sync.aligned.m8n8.x4.shared.b16 {%0,%1,%2,%3}, [%4];"
                 : "=r"(r[0]), "=r"(r[1]), "=r"(r[2]), "=r"(r[3]) : "r"(addr));
}
__device__ __forceinline__ void mma16816(float* d, const uint32_t* a, uint32_t b0, uint32_t b1) {
    asm volatile(
        "mma.sync.aligned.m16n8k16.row.col.f32.f16.f16.f32 "
        "{%0,%1,%2,%3}, {%4,%5,%6,%7}, {%8,%9}, {%0,%1,%2,%3};"
        : "+f"(d[0]), "+f"(d[1]), "+f"(d[2]), "+f"(d[3])
        : "r"(a[0]), "r"(a[1]), "r"(a[2]), "r"(a[3]), "r"(b0), "r"(b1));
}

// ---------------- K0: fused prep (encconv | w1conv | qproj) ----------------
__global__ __launch_bounds__(256) void prep_kernel(const float* __restrict__ enc,
                                                   const int* __restrict__ lens,
                                                   const float* __restrict__ W1,
                                                   const float* __restrict__ dec,
                                                   const float* __restrict__ W2) {
    const int blk = blockIdx.x;
    const int tid = threadIdx.x;

    if (blk < 8192) {                       // ---- encconv (16 rows each) ----
        const int b    = blk >> 7;
        const int row0 = (blk & 127) << 4;
        const int lim  = ((lens[b] + 127) >> 7) << 7;
        if (row0 >= lim) return;
        const size_t base = ((size_t)b * S_ + row0) * H_;
        const float4* src = (const float4*)(enc + base);
        uint2* dh = (uint2*)(g_encF + base);
#pragma unroll 4
        for (int i = tid; i < 2048; i += 256) {
            float4 v = src[i];
            dh[i] = make_uint2(cvtf2(v.x, v.y), cvtf2(v.z, v.w));
        }
    } else if (blk < 9216) {                // ---- w1conv ----
        int idx = (blk - 8192) * 256 + tid; // idx = n*512 + k
        int n = idx >> 9, k = idx & 511;
        g_w1tF[idx] = __float2half(W1[(size_t)k * H_ + n]);
    } else {                                // ---- qproj ----
        const int b = blk - 9216;
        __shared__ float xs[H_];
        xs[tid] = dec[b * H_ + tid];
        xs[tid + 256] = dec[b * H_ + tid + 256];
        __syncthreads();
        float a0 = 0.f, a1 = 0.f;
#pragma unroll 8
        for (int h = 0; h < H_; ++h) {
            float x = xs[h];
            a0 += x * W2[(size_t)h * H_ + tid];
            a1 += x * W2[(size_t)h * H_ + tid + 256];
        }
        g_q[b * H_ + tid] = a0;
        g_q[b * H_ + tid + 256] = a1;
    }
}

// ---------------- K1: fp16 mma.sync energy GEMM ----------------
// CTA: 128 rows x 256 cols, K=512 in 4 chunks of 128, 2-stage cp.async
// pipeline (96KB/stage -> only 4 __syncthreads in the mainloop).
// 16 warps, warp grid 4M x 4N, warp tile 32x64. 1 CTA/SM (193KB smem).
// Each chunk is stored as two 64-k sub-blocks with 128B SW128 rows;
// sub index = kq>>2 (aligned ADD), kq&3 folds into the swizzle via XOR.
#define STG    98304       // per-stage: A 32KB + B 64KB
#define OFF_B  32768
#define ASUB   16384       // A sub-block stride (128 rows x 128B)
#define BSUB   32768       // B sub-block stride (256 rows x 128B)
#define DSMEM  (1024 + 2 * STG)   // 197632

__global__ __launch_bounds__(512, 1) void energy_kernel(const float* __restrict__ Vv,
                                                        const int* __restrict__ lens) {
    // grid: b*32 + tile*2 + nc
    const int nc   = blockIdx.x & 1;
    const int tile = (blockIdx.x >> 1) & 15;
    const int b    = blockIdx.x >> 5;
    const int row0 = tile << 7;
    const int n0   = nc << 8;
    if (row0 >= lens[b]) return;

    extern __shared__ char dsm[];
    __shared__ float qs[256], Vs[256], es4[4][128];

    const int tid  = threadIdx.x;
    const int wid  = tid >> 5;
    const int lane = tid & 31;
    const int mbase = (wid & 3) << 5;   // 0..96
    const int nidx  = wid >> 2;         // 0..3
    const int nbase = nidx << 6;        // 0..192

    const uint32_t dynB = smem_u32(dsm);
    const uint32_t tb   = (dynB + 1023u) & ~1023u;

    if (tid < 256) {
        qs[tid] = g_q[b * H_ + n0 + tid];
        Vs[tid] = Vv[n0 + tid];
    }

    // cp.async slots (per 128-k chunk):
    //  A: ra = tid>>2 (0..127), qa = tid&3 -> 64B of the row (4x cp16)
    //  B: rb2 = tid>>1 (0..255), seg = tid&1 -> 128B sub-row (8x cp16)
    const int ra = tid >> 2, qa = tid & 3;
    const int rb2 = tid >> 1, seg = tid & 1;
    const __half* aSrc = g_encF + ((size_t)b * S_ + row0 + ra) * H_ + qa * 32;
    const __half* bSrc = g_w1tF + ((size_t)(n0 + rb2)) * H_ + seg * 64;
    uint32_t offA[4], offB[8];
#pragma unroll
    for (int j = 0; j < 4; ++j)
        offA[j] = (uint32_t)(qa >> 1) * ASUB
                + SW128((uint32_t)(ra * 128 + (qa & 1) * 64 + j * 16));
#pragma unroll
    for (int j = 0; j < 8; ++j)
        offB[j] = (uint32_t)seg * BSUB + SW128((uint32_t)(rb2 * 128 + j * 16));

    // ldmatrix swizzled bases (sub-block 0); (kq&3)*32 folds via XOR,
    // (kq>>2)*ASUB|BSUB and stage offsets are aligned ADDs.
    const int rbl = (((lane & 15) >> 3) << 3) + (lane & 7);
    const int c16 = (lane >> 4) << 4;
    const uint32_t aA0 = tb + SW128((uint32_t)((mbase + rbl) * 128 + c16));
    const uint32_t aA1 = tb + SW128((uint32_t)((mbase + 16 + rbl) * 128 + c16));
    const uint32_t aB0 = tb + OFF_B + SW128((uint32_t)((nbase + rbl) * 128 + c16));
    const uint32_t aB1 = tb + OFF_B + SW128((uint32_t)((nbase + 16 + rbl) * 128 + c16));
    const uint32_t aB2 = tb + OFF_B + SW128((uint32_t)((nbase + 32 + rbl) * 128 + c16));
    const uint32_t aB3 = tb + OFF_B + SW128((uint32_t)((nbase + 48 + rbl) * 128 + c16));

    float acc[2][8][4];
#pragma unroll
    for (int i = 0; i < 2; ++i)
#pragma unroll
        for (int j = 0; j < 8; ++j)
#pragma unroll
            for (int q = 0; q < 4; ++q) acc[i][j][q] = 0.f;

    // prologue: chunk 0 -> stage 0
#pragma unroll
    for (int j = 0; j < 4; ++j) cp16(tb + offA[j], aSrc + j * 8);
#pragma unroll
    for (int j = 0; j < 8; ++j) cp16(tb + OFF_B + offB[j], bSrc + j * 8);
    cp_commit();

#pragma unroll
    for (int kc = 0; kc < 4; ++kc) {
        cp_wait0();          // current chunk's data has landed (own group)
        __syncthreads();     // ...and is visible; prior chunk's reads done

        if (kc < 3) {        // prefetch next chunk into the other stage
            const int ns = kc + 1;
            const uint32_t sb = tb + (ns & 1) * STG;
#pragma unroll
            for (int j = 0; j < 4; ++j) cp16(sb + offA[j], aSrc + ns * 128 + j * 8);
#pragma unroll
            for (int j = 0; j < 8; ++j) cp16(sb + OFF_B + offB[j], bSrc + ns * 128 + j * 8);
            cp_commit();
        }

        const uint32_t so = (kc & 1) * STG;
#pragma unroll
        for (int kq = 0; kq < 8; ++kq) {
            const uint32_t subA = so + (uint32_t)(kq >> 2) * ASUB;
            const uint32_t subB = so + (uint32_t)(kq >> 2) * BSUB;
            const uint32_t kk = (uint32_t)((kq & 3) << 5);
            uint32_t a0[4], a1[4], bf[4][4];
            ldmx4(a0, (aA0 + subA) ^ kk);
            ldmx4(a1, (aA1 + subA) ^ kk);
            ldmx4(bf[0], (aB0 + subB) ^ kk);
            ldmx4(bf[1], (aB1 + subB) ^ kk);
            ldmx4(bf[2], (aB2 + subB) ^ kk);
            ldmx4(bf[3], (aB3 + subB) ^ kk);
#pragma unroll
            for (int t = 0; t < 4; ++t) {
                mma16816(acc[0][t * 2],     a0, bf[t][0], bf[t][2]);
                mma16816(acc[0][t * 2 + 1], a0, bf[t][1], bf[t][3]);
                mma16816(acc[1][t * 2],     a1, bf[t][0], bf[t][2]);
                mma16816(acc[1][t * 2 + 1], a1, bf[t][1], bf[t][3]);
            }
        }
    }
    __syncthreads();

    // ---- epilogue: per-(ngroup,row) race-free slots, then combine ----
    const int gid = lane >> 2, t4 = lane & 3;
#pragma unroll
    for (int mt = 0; mt < 2; ++mt) {
        float s0 = 0.f, s1 = 0.f;
#pragma unroll
        for (int nt = 0; nt < 8; ++nt) {
            int c = nbase + nt * 8 + t4 * 2;
            float q0 = qs[c], q1 = qs[c + 1], v0 = Vs[c], v1 = Vs[c + 1];
            float* d = acc[mt][nt];
            s0 += tanh_fast(d[0] + q0) * v0 + tanh_fast(d[1] + q1) * v1;
            s1 += tanh_fast(d[2] + q0) * v0 + tanh_fast(d[3] + q1) * v1;
        }
        s0 += __shfl_xor_sync(0xffffffffu, s0, 1);
        s0 += __shfl_xor_sync(0xffffffffu, s0, 2);
        s1 += __shfl_xor_sync(0xffffffffu, s1, 1);
        s1 += __shfl_xor_sync(0xffffffffu, s1, 2);
        if (t4 == 0) {
            es4[nidx][mbase + mt * 16 + gid]     = s0;
            es4[nidx][mbase + mt * 16 + gid + 8] = s1;
        }
    }
    __syncthreads();
    if (tid < 128)
        g_ep[nc][b * S_ + row0 + tid] =
            es4[0][tid] + es4[1][tid] + es4[2][tid] + es4[3][tid];
}

// ---------------- K2: single-pass softmax (no max needed: |e| <= sum|V| < 87) --
__global__ __launch_bounds__(256) void stats_kernel(const int* __restrict__ lens,
                                                    float* __restrict__ out) {
    int b = blockIdx.x;
    int tid = threadIdx.x;
    int len = lens[b];
    __shared__ float red[256];

    out[b * H_ + tid] = 0.f;
    out[b * H_ + tid + 256] = 0.f;

    float sm = 0.f;
    for (int s = tid; s < S_; s += 256) {
        int i = b * S_ + s;
        float w = (s < len) ? __expf(g_ep[0][i] + g_ep[1][i]) : 0.f;
        g_energy[i] = w;
        sm += w;
    }
    red[tid] = sm;
    __syncthreads();
    for (int o = 128; o > 0; o >>= 1) {
        if (tid < o) red[tid] += red[tid + o];
        __syncthreads();
    }
    if (tid == 0) g_invden[b] = 1.0f / red[0];
}

// ---------------- K3: context = sum_s w[s] * enc_fp16[b,s,:] ----------------
__global__ __launch_bounds__(256) void context_kernel(const int* __restrict__ lens,
                                                      float* __restrict__ out) {
    const int b     = blockIdx.x >> 5;
    const int chunk = blockIdx.x & 31;
    const int row0  = chunk * 64;
    const int len   = lens[b];
    if (row0 >= len) return;

    __shared__ float ws[64];
    const int tid = threadIdx.x;
    if (tid < 64)
        ws[tid] = g_energy[b * S_ + row0 + tid] * g_invden[b];
    __syncthreads();

    const int smax = min(64, len - row0);
    const __half2* base = (const __half2*)(g_encF + ((size_t)b * S_ + row0) * H_) + tid;
    float c0 = 0.f, c1 = 0.f;
#pragma unroll 8
    for (int s = 0; s < smax; ++s) {
        float2 f = __half22float2(base[s * 256]);
        float w = ws[s];
        c0 += w * f.x;
        c1 += w * f.y;
    }
    atomicAdd(&out[b * H_ + tid * 2], c0);
    atomicAdd(&out[b * H_ + tid * 2 + 1], c1);
}

// ---------------- launch ----------------
extern "C" void kernel_launch(void* const* d_in, const int* in_sizes, int n_in,
                              void* d_out, int out_size) {
    const float* dec  = (const float*)d_in[0];
    const float* enc  = (const float*)d_in[1];
    const int*   lens = (const int*)d_in[2];
    const float* W1   = (const float*)d_in[3];
    const float* W2   = (const float*)d_in[4];
    const float* V    = (const float*)d_in[5];
    float* out = (float*)d_out;

    cudaFuncSetAttribute(energy_kernel,
                         cudaFuncAttributeMaxDynamicSharedMemorySize, DSMEM);

    prep_kernel<<<9280, 256>>>(enc, lens, W1, dec, W2);
    energy_kernel<<<B_ * 32, 512, DSMEM>>>(V, lens);
    stats_kernel<<<B_, 256>>>(lens, out);
    context_kernel<<<B_ * (S_ / 64), 256>>>(lens, out);
}

// round 13
// speedup vs baseline: 1.1475x; 1.1475x over previous
#include <cuda_runtime.h>
#include <cuda_fp16.h>
#include <cstdint>
#include <cstddef>

#define B_ 64
#define S_ 2048
#define H_ 512

// ---------------- scratch (no allocations allowed) ----------------
__device__ float g_q[B_ * H_];            // query projection [B,H]
__device__ float g_ep[2][B_ * S_];        // energy partials per n-half
__device__ float g_energy[B_ * S_];       // exp(energy) weights (0 when masked)
__device__ float g_invden[B_];
__device__ int   g_cnt[B_];               // CTA completion counters per batch
__device__ __half g_w1tF[H_ * H_];        // W1^T fp16 [n][k]
__device__ __half g_encF[(size_t)B_ * S_ * H_];  // enc fp16

// ---------------- helpers ----------------
__device__ __forceinline__ uint32_t smem_u32(const void* p) {
    uint32_t a;
    asm("{ .reg .u64 t; cvta.to.shared.u64 t, %1; cvt.u32.u64 %0, t; }" : "=r"(a) : "l"(p));
    return a;
}
#define SW128(o) ((o) ^ (((o) >> 3) & 0x70))

__device__ __forceinline__ uint32_t cvtf2(float lo, float hi) {  // f16x2 {hi,lo}
    uint32_t r;
    asm("cvt.rn.f16x2.f32 %0, %1, %2;" : "=r"(r) : "f"(hi), "f"(lo));
    return r;
}
__device__ __forceinline__ float tanh_fast(float x) {
    float e = __expf(2.0f * x);
    return 1.0f - __fdividef(2.0f, e + 1.0f);
}
__device__ __forceinline__ void cp16(uint32_t dst, const void* src) {
    asm volatile("cp.async.cg.shared.global [%0], [%1], 16;" :: "r"(dst), "l"(src) : "memory");
}
__device__ __forceinline__ void cp_commit() {
    asm volatile("cp.async.commit_group;" ::: "memory");
}
__device__ __forceinline__ void cp_wait2() {
    asm volatile("cp.async.wait_group 2;" ::: "memory");
}
__device__ __forceinline__ void cp_wait1() {
    asm volatile("cp.async.wait_group 1;" ::: "memory");
}
__device__ __forceinline__ void cp_wait0() {
    asm volatile("cp.async.wait_group 0;" ::: "memory");
}
__device__ __forceinline__ void ldmx4(uint32_t* r, uint32_t addr) {
    asm volatile("ldmatrix.sync.aligned.m8n8.x4.shared.b16 {%0,%1,%2,%3}, [%4];"
                 : "=r"(r[0]), "=r"(r[1]), "=r"(r[2]), "=r"(r[3]) : "r"(addr));
}
__device__ __forceinline__ void mma16816(float* d, const uint32_t* a, uint32_t b0, uint32_t b1) {
    asm volatile(
        "mma.sync.aligned.m16n8k16.row.col.f32.f16.f16.f32 "
        "{%0,%1,%2,%3}, {%4,%5,%6,%7}, {%8,%9}, {%0,%1,%2,%3};"
        : "+f"(d[0]), "+f"(d[1]), "+f"(d[2]), "+f"(d[3])
        : "r"(a[0]), "r"(a[1]), "r"(a[2]), "r"(a[3]), "r"(b0), "r"(b1));
}

// ---------------- K0: fused prep (encconv | w1conv | qproj+reset) -----------
__global__ __launch_bounds__(256) void prep_kernel(const float* __restrict__ enc,
                                                   const int* __restrict__ lens,
                                                   const float* __restrict__ W1,
                                                   const float* __restrict__ dec,
                                                   const float* __restrict__ W2,
                                                   float* __restrict__ out) {
    const int blk = blockIdx.x;
    const int tid = threadIdx.x;

    if (blk < 8192) {                       // ---- encconv (16 rows each) ----
        const int b    = blk >> 7;
        const int row0 = (blk & 127) << 4;
        const int lim  = ((lens[b] + 127) >> 7) << 7;
        if (row0 >= lim) return;
        const size_t base = ((size_t)b * S_ + row0) * H_;
        const float4* src = (const float4*)(enc + base);
        uint2* dh = (uint2*)(g_encF + base);
#pragma unroll 4
        for (int i = tid; i < 2048; i += 256) {
            float4 v = src[i];
            dh[i] = make_uint2(cvtf2(v.x, v.y), cvtf2(v.z, v.w));
        }
    } else if (blk < 9216) {                // ---- w1conv ----
        int idx = (blk - 8192) * 256 + tid; // idx = n*512 + k
        int n = idx >> 9, k = idx & 511;
        g_w1tF[idx] = __float2half(W1[(size_t)k * H_ + n]);
    } else {                                // ---- qproj + per-batch resets ----
        const int b = blk - 9216;
        __shared__ float xs[H_];
        xs[tid] = dec[b * H_ + tid];
        xs[tid + 256] = dec[b * H_ + tid + 256];
        if (tid == 0) g_cnt[b] = 0;
        out[b * H_ + tid] = 0.f;
        out[b * H_ + tid + 256] = 0.f;
        __syncthreads();
        float a0 = 0.f, a1 = 0.f;
#pragma unroll 8
        for (int h = 0; h < H_; ++h) {
            float x = xs[h];
            a0 += x * W2[(size_t)h * H_ + tid];
            a1 += x * W2[(size_t)h * H_ + tid + 256];
        }
        g_q[b * H_ + tid] = a0;
        g_q[b * H_ + tid + 256] = a1;
    }
}

// ---------------- K1: fp16 mma.sync energy GEMM (+fused softmax tail) -------
// CTA: 128 rows x 256 cols, K=512 in 8 chunks of 64, 4-stage cp.async pipeline.
// 16 warps, warp grid 4M x 4N, warp tile 32x64. 1 CTA/SM (193KB smem).
// The 32nd (last) CTA of each batch computes exp-weights + 1/sum inline.
#define STG    49152       // per-stage: A 16KB + B 32KB
#define OFF_B  16384
#define DSMEM  (1024 + 4 * STG)   // 197632

__global__ __launch_bounds__(512, 1) void energy_kernel(const float* __restrict__ Vv,
                                                        const int* __restrict__ lens) {
    // grid: b*32 + tile*2 + nc
    const int nc   = blockIdx.x & 1;
    const int tile = (blockIdx.x >> 1) & 15;
    const int b    = blockIdx.x >> 5;
    const int row0 = tile << 7;
    const int n0   = nc << 8;
    const int len  = lens[b];
    const int tid  = threadIdx.x;

    __shared__ int done;
    __shared__ float qs[256], Vs[256], es4[4][128];

    if (row0 >= len) {   // fully masked tile: just arrive at the counter
        if (tid == 0) done = atomicAdd(&g_cnt[b], 1);
        __syncthreads();
        if (done != 31) return;
        // fall through to softmax tail below (skip GEMM entirely)
    } else {
        extern __shared__ char dsm[];
        const int wid  = tid >> 5;
        const int lane = tid & 31;
        const int mbase = (wid & 3) << 5;   // 0..96
        const int nidx  = wid >> 2;         // 0..3
        const int nbase = nidx << 6;        // 0..192

        const uint32_t dynB = smem_u32(dsm);
        const uint32_t tb   = (dynB + 1023u) & ~1023u;

        if (tid < 256) {
            qs[tid] = g_q[b * H_ + n0 + tid];
            Vs[tid] = Vv[n0 + tid];
        }

        // cp.async slots: A: ra = tid>>2, qa = tid&3 (2x cp16)
        //                 B: rb2 = tid>>1, seg = tid&1 (4x cp16)
        const int ra = tid >> 2, qa = tid & 3;
        const int rb2 = tid >> 1, seg = tid & 1;
        const __half* aSrc = g_encF + ((size_t)b * S_ + row0 + ra) * H_ + qa * 16;
        const __half* bSrc = g_w1tF + ((size_t)(n0 + rb2)) * H_ + seg * 32;
        uint32_t offA[2], offB[4];
#pragma unroll
        for (int j = 0; j < 2; ++j)
            offA[j] = SW128((uint32_t)(ra * 128 + qa * 32 + j * 16));
#pragma unroll
        for (int j = 0; j < 4; ++j)
            offB[j] = SW128((uint32_t)(rb2 * 128 + seg * 64 + j * 16));

        // ldmatrix swizzled bases; kq*32 folds with XOR (bits 5..6), stage adds.
        const int rbl = (((lane & 15) >> 3) << 3) + (lane & 7);
        const int c16 = (lane >> 4) << 4;
        const uint32_t aA0 = tb + SW128((uint32_t)((mbase + rbl) * 128 + c16));
        const uint32_t aA1 = tb + SW128((uint32_t)((mbase + 16 + rbl) * 128 + c16));
        const uint32_t aB0 = tb + OFF_B + SW128((uint32_t)((nbase + rbl) * 128 + c16));
        const uint32_t aB1 = tb + OFF_B + SW128((uint32_t)((nbase + 16 + rbl) * 128 + c16));
        const uint32_t aB2 = tb + OFF_B + SW128((uint32_t)((nbase + 32 + rbl) * 128 + c16));
        const uint32_t aB3 = tb + OFF_B + SW128((uint32_t)((nbase + 48 + rbl) * 128 + c16));

        float acc[2][8][4];
#pragma unroll
        for (int i = 0; i < 2; ++i)
#pragma unroll
            for (int j = 0; j < 8; ++j)
#pragma unroll
                for (int q = 0; q < 4; ++q) acc[i][j][q] = 0.f;

        // prologue: stages 0,1,2
#pragma unroll
        for (int s = 0; s < 3; ++s) {
            const uint32_t sb = tb + s * STG;
            cp16(sb + offA[0], aSrc + s * 64);
            cp16(sb + offA[1], aSrc + s * 64 + 8);
#pragma unroll
            for (int j = 0; j < 4; ++j)
                cp16(sb + OFF_B + offB[j], bSrc + s * 64 + j * 8);
            cp_commit();
        }

#pragma unroll
        for (int kc = 0; kc < 8; ++kc) {
            if (kc <= 5) cp_wait2();
            else if (kc == 6) cp_wait1();
            else cp_wait0();
            __syncthreads();

            if (kc < 5) {
                const int ns = kc + 3;
                const uint32_t sb = tb + (ns & 3) * STG;
                cp16(sb + offA[0], aSrc + ns * 64);
                cp16(sb + offA[1], aSrc + ns * 64 + 8);
#pragma unroll
                for (int j = 0; j < 4; ++j)
                    cp16(sb + OFF_B + offB[j], bSrc + ns * 64 + j * 8);
                cp_commit();
            }

            const uint32_t so = (kc & 3) * STG;
#pragma unroll
            for (int kq = 0; kq < 4; ++kq) {
                const uint32_t kk = (uint32_t)(kq << 5);
                uint32_t a0[4], a1[4], bf[4][4];
                ldmx4(a0, (aA0 + so) ^ kk);
                ldmx4(a1, (aA1 + so) ^ kk);
                ldmx4(bf[0], (aB0 + so) ^ kk);
                ldmx4(bf[1], (aB1 + so) ^ kk);
                ldmx4(bf[2], (aB2 + so) ^ kk);
                ldmx4(bf[3], (aB3 + so) ^ kk);
#pragma unroll
                for (int t = 0; t < 4; ++t) {
                    mma16816(acc[0][t * 2],     a0, bf[t][0], bf[t][2]);
                    mma16816(acc[0][t * 2 + 1], a0, bf[t][1], bf[t][3]);
                    mma16816(acc[1][t * 2],     a1, bf[t][0], bf[t][2]);
                    mma16816(acc[1][t * 2 + 1], a1, bf[t][1], bf[t][3]);
                }
            }
        }
        __syncthreads();

        // ---- epilogue: per-(ngroup,row) race-free slots, then combine ----
        const int gid = lane >> 2, t4 = lane & 3;
#pragma unroll
        for (int mt = 0; mt < 2; ++mt) {
            float s0 = 0.f, s1 = 0.f;
#pragma unroll
            for (int nt = 0; nt < 8; ++nt) {
                int c = nbase + nt * 8 + t4 * 2;
                float q0 = qs[c], q1 = qs[c + 1], v0 = Vs[c], v1 = Vs[c + 1];
                float* d = acc[mt][nt];
                s0 += tanh_fast(d[0] + q0) * v0 + tanh_fast(d[1] + q1) * v1;
                s1 += tanh_fast(d[2] + q0) * v0 + tanh_fast(d[3] + q1) * v1;
            }
            s0 += __shfl_xor_sync(0xffffffffu, s0, 1);
            s0 += __shfl_xor_sync(0xffffffffu, s0, 2);
            s1 += __shfl_xor_sync(0xffffffffu, s1, 1);
            s1 += __shfl_xor_sync(0xffffffffu, s1, 2);
            if (t4 == 0) {
                es4[nidx][mbase + mt * 16 + gid]     = s0;
                es4[nidx][mbase + mt * 16 + gid + 8] = s1;
            }
        }
        __syncthreads();
        if (tid < 128)
            g_ep[nc][b * S_ + row0 + tid] =
                es4[0][tid] + es4[1][tid] + es4[2][tid] + es4[3][tid];

        // arrive: make g_ep globally visible, then bump the counter
        __threadfence();
        __syncthreads();
        if (tid == 0) done = atomicAdd(&g_cnt[b], 1);
        __syncthreads();
        if (done != 31) return;
    }

    // ---- softmax tail (exactly one CTA per batch reaches here) ----
    // single-pass: |e| <= sum|V| < 87 so exp never overflows in fp32.
    {
        float sm = 0.f;
        for (int s = tid; s < S_; s += 512) {
            int i = b * S_ + s;
            float w = (s < len) ? __expf(g_ep[0][i] + g_ep[1][i]) : 0.f;
            g_energy[i] = w;
            sm += w;
        }
#pragma unroll
        for (int o = 16; o > 0; o >>= 1)
            sm += __shfl_xor_sync(0xffffffffu, sm, o);
        if ((tid & 31) == 0) es4[0][tid >> 5] = sm;
        __syncthreads();
        if (tid == 0) {
            float tot = 0.f;
#pragma unroll
            for (int w = 0; w < 16; ++w) tot += es4[0][w];
            g_invden[b] = 1.0f / tot;
        }
    }
}

// ---------------- K2: context = sum_s w[s] * enc_fp16[b,s,:] ----------------
__global__ __launch_bounds__(256) void context_kernel(const int* __restrict__ lens,
                                                      float* __restrict__ out) {
    const int b     = blockIdx.x >> 5;
    const int chunk = blockIdx.x & 31;
    const int row0  = chunk * 64;
    const int len   = lens[b];
    if (row0 >= len) return;

    __shared__ float ws[64];
    const int tid = threadIdx.x;
    if (tid < 64)
        ws[tid] = g_energy[b * S_ + row0 + tid] * g_invden[b];
    __syncthreads();

    const int smax = min(64, len - row0);
    const __half2* base = (const __half2*)(g_encF + ((size_t)b * S_ + row0) * H_) + tid;
    float c0 = 0.f, c1 = 0.f;
#pragma unroll 8
    for (int s = 0; s < smax; ++s) {
        float2 f = __half22float2(base[s * 256]);
        float w = ws[s];
        c0 += w * f.x;
        c1 += w * f.y;
    }
    atomicAdd(&out[b * H_ + tid * 2], c0);
    atomicAdd(&out[b * H_ + tid * 2 + 1], c1);
}

// ---------------- launch ----------------
extern "C" void kernel_launch(void* const* d_in, const int* in_sizes, int n_in,
                              void* d_out, int out_size) {
    const float* dec  = (const float*)d_in[0];
    const float* enc  = (const float*)d_in[1];
    const int*   lens = (const int*)d_in[2];
    const float* W1   = (const float*)d_in[3];
    const float* W2   = (const float*)d_in[4];
    const float* V    = (const float*)d_in[5];
    float* out = (float*)d_out;

    cudaFuncSetAttribute(energy_kernel,
                         cudaFuncAttributeMaxDynamicSharedMemorySize, DSMEM);

    prep_kernel<<<9280, 256>>>(enc, lens, W1, dec, W2, out);
    energy_kernel<<<B_ * 32, 512, DSMEM>>>(V, lens);
    context_kernel<<<B_ * (S_ / 64), 256>>>(lens, out);
}

// round 14
// speedup vs baseline: 1.1913x; 1.0382x over previous
#include <cuda_runtime.h>
#include <cuda_fp16.h>
#include <cstdint>
#include <cstddef>

#define B_ 64
#define S_ 2048
#define H_ 512

// ---------------- scratch (no allocations allowed) ----------------
__device__ float g_q[B_ * H_];            // query projection [B,H]
__device__ float g_ep[2][B_ * S_];        // energy partials per n-half
__device__ float g_energy[B_ * S_];       // exp(energy) weights (0 when masked)
__device__ float g_invden[B_];
__device__ __half g_w1tF[H_ * H_];        // W1^T fp16 [n][k]
__device__ __half g_encF[(size_t)B_ * S_ * H_];  // enc fp16

// ---------------- helpers ----------------
__device__ __forceinline__ uint32_t smem_u32(const void* p) {
    uint32_t a;
    asm("{ .reg .u64 t; cvta.to.shared.u64 t, %1; cvt.u32.u64 %0, t; }" : "=r"(a) : "l"(p));
    return a;
}
#define SW128(o) ((o) ^ (((o) >> 3) & 0x70))

__device__ __forceinline__ uint32_t cvtf2(float lo, float hi) {  // f16x2 {hi,lo}
    uint32_t r;
    asm("cvt.rn.f16x2.f32 %0, %1, %2;" : "=r"(r) : "f"(hi), "f"(lo));
    return r;
}
__device__ __forceinline__ float tanh_fast(float x) {
    float e = __expf(2.0f * x);
    return 1.0f - __fdividef(2.0f, e + 1.0f);
}
__device__ __forceinline__ void cp16(uint32_t dst, const void* src) {
    asm volatile("cp.async.cg.shared.global [%0], [%1], 16;" :: "r"(dst), "l"(src) : "memory");
}
__device__ __forceinline__ void cp_commit() {
    asm volatile("cp.async.commit_group;" ::: "memory");
}
__device__ __forceinline__ void cp_wait2() {
    asm volatile("cp.async.wait_group 2;" ::: "memory");
}
__device__ __forceinline__ void cp_wait1() {
    asm volatile("cp.async.wait_group 1;" ::: "memory");
}
__device__ __forceinline__ void cp_wait0() {
    asm volatile("cp.async.wait_group 0;" ::: "memory");
}
__device__ __forceinline__ void ldmx4(uint32_t* r, uint32_t addr) {
    asm volatile("ldmatrix.sync.aligned.m8n8.x4.shared.b16 {%0,%1,%2,%3}, [%4];"
                 : "=r"(r[0]), "=r"(r[1]), "=r"(r[2]), "=r"(r[3]) : "r"(addr));
}
__device__ __forceinline__ void mma16816(float* d, const uint32_t* a, uint32_t b0, uint32_t b1) {
    asm volatile(
        "mma.sync.aligned.m16n8k16.row.col.f32.f16.f16.f32 "
        "{%0,%1,%2,%3}, {%4,%5,%6,%7}, {%8,%9}, {%0,%1,%2,%3};"
        : "+f"(d[0]), "+f"(d[1]), "+f"(d[2]), "+f"(d[3])
        : "r"(a[0]), "r"(a[1]), "r"(a[2]), "r"(a[3]), "r"(b0), "r"(b1));
}

// ---------------- K0: fused prep (encconv | w1conv | qproj) ----------------
__global__ __launch_bounds__(256) void prep_kernel(const float* __restrict__ enc,
                                                   const int* __restrict__ lens,
                                                   const float* __restrict__ W1,
                                                   const float* __restrict__ dec,
                                                   const float* __restrict__ W2) {
    const int blk = blockIdx.x;
    const int tid = threadIdx.x;

    if (blk < 8192) {                       // ---- encconv (16 rows each) ----
        const int b    = blk >> 7;
        const int row0 = (blk & 127) << 4;
        const int lim  = ((lens[b] + 127) >> 7) << 7;
        if (row0 >= lim) return;
        const size_t base = ((size_t)b * S_ + row0) * H_;
        const float4* src = (const float4*)(enc + base);
        uint2* dh = (uint2*)(g_encF + base);
        // batch all loads first (MLP=8, 128B/thread in flight), then convert+store
        float4 v[8];
#pragma unroll
        for (int j = 0; j < 8; ++j) v[j] = src[tid + (j << 8)];
#pragma unroll
        for (int j = 0; j < 8; ++j)
            dh[tid + (j << 8)] = make_uint2(cvtf2(v[j].x, v[j].y),
                                            cvtf2(v[j].z, v[j].w));
    } else if (blk < 9216) {                // ---- w1conv ----
        int idx = (blk - 8192) * 256 + tid; // idx = n*512 + k
        int n = idx >> 9, k = idx & 511;
        g_w1tF[idx] = __float2half(W1[(size_t)k * H_ + n]);
    } else {                                // ---- qproj ----
        const int b = blk - 9216;
        __shared__ float xs[H_];
        xs[tid] = dec[b * H_ + tid];
        xs[tid + 256] = dec[b * H_ + tid + 256];
        __syncthreads();
        float a0 = 0.f, a1 = 0.f;
#pragma unroll 8
        for (int h = 0; h < H_; ++h) {
            float x = xs[h];
            a0 += x * W2[(size_t)h * H_ + tid];
            a1 += x * W2[(size_t)h * H_ + tid + 256];
        }
        g_q[b * H_ + tid] = a0;
        g_q[b * H_ + tid + 256] = a1;
    }
}

// ---------------- K1: fp16 mma.sync energy GEMM ----------------
// CTA: 128 rows x 256 cols, K=512 in 8 chunks of 64, 4-stage cp.async pipeline.
// 16 warps, warp grid 4M x 4N, warp tile 32x64. 1 CTA/SM (193KB smem).
#define STG    49152       // per-stage: A 16KB + B 32KB
#define OFF_B  16384
#define DSMEM  (1024 + 4 * STG)   // 197632

__global__ __launch_bounds__(512, 1) void energy_kernel(const float* __restrict__ Vv,
                                                        const int* __restrict__ lens) {
    // grid: b*32 + tile*2 + nc
    const int nc   = blockIdx.x & 1;
    const int tile = (blockIdx.x >> 1) & 15;
    const int b    = blockIdx.x >> 5;
    const int row0 = tile << 7;
    const int n0   = nc << 8;
    if (row0 >= lens[b]) return;

    extern __shared__ char dsm[];
    __shared__ float qs[256], Vs[256], es4[4][128];

    const int tid  = threadIdx.x;
    const int wid  = tid >> 5;
    const int lane = tid & 31;
    const int mbase = (wid & 3) << 5;   // 0..96
    const int nidx  = wid >> 2;         // 0..3
    const int nbase = nidx << 6;        // 0..192

    const uint32_t dynB = smem_u32(dsm);
    const uint32_t tb   = (dynB + 1023u) & ~1023u;

    if (tid < 256) {
        qs[tid] = g_q[b * H_ + n0 + tid];
        Vs[tid] = Vv[n0 + tid];
    }

    // cp.async slots: A: ra = tid>>2, qa = tid&3 (2x cp16)
    //                 B: rb2 = tid>>1, seg = tid&1 (4x cp16)
    const int ra = tid >> 2, qa = tid & 3;
    const int rb2 = tid >> 1, seg = tid & 1;
    const __half* aSrc = g_encF + ((size_t)b * S_ + row0 + ra) * H_ + qa * 16;
    const __half* bSrc = g_w1tF + ((size_t)(n0 + rb2)) * H_ + seg * 32;
    uint32_t offA[2], offB[4];
#pragma unroll
    for (int j = 0; j < 2; ++j)
        offA[j] = SW128((uint32_t)(ra * 128 + qa * 32 + j * 16));
#pragma unroll
    for (int j = 0; j < 4; ++j)
        offB[j] = SW128((uint32_t)(rb2 * 128 + seg * 64 + j * 16));

    // ldmatrix swizzled bases; kq*32 folds with XOR (bits 5..6), stage adds.
    const int rbl = (((lane & 15) >> 3) << 3) + (lane & 7);
    const int c16 = (lane >> 4) << 4;
    const uint32_t aA0 = tb + SW128((uint32_t)((mbase + rbl) * 128 + c16));
    const uint32_t aA1 = tb + SW128((uint32_t)((mbase + 16 + rbl) * 128 + c16));
    const uint32_t aB0 = tb + OFF_B + SW128((uint32_t)((nbase + rbl) * 128 + c16));
    const uint32_t aB1 = tb + OFF_B + SW128((uint32_t)((nbase + 16 + rbl) * 128 + c16));
    const uint32_t aB2 = tb + OFF_B + SW128((uint32_t)((nbase + 32 + rbl) * 128 + c16));
    const uint32_t aB3 = tb + OFF_B + SW128((uint32_t)((nbase + 48 + rbl) * 128 + c16));

    float acc[2][8][4];
#pragma unroll
    for (int i = 0; i < 2; ++i)
#pragma unroll
        for (int j = 0; j < 8; ++j)
#pragma unroll
            for (int q = 0; q < 4; ++q) acc[i][j][q] = 0.f;

    // prologue: stages 0,1,2
#pragma unroll
    for (int s = 0; s < 3; ++s) {
        const uint32_t sb = tb + s * STG;
        cp16(sb + offA[0], aSrc + s * 64);
        cp16(sb + offA[1], aSrc + s * 64 + 8);
#pragma unroll
        for (int j = 0; j < 4; ++j)
            cp16(sb + OFF_B + offB[j], bSrc + s * 64 + j * 8);
        cp_commit();
    }

#pragma unroll
    for (int kc = 0; kc < 8; ++kc) {
        if (kc <= 5) cp_wait2();
        else if (kc == 6) cp_wait1();
        else cp_wait0();
        __syncthreads();

        if (kc < 5) {
            const int ns = kc + 3;
            const uint32_t sb = tb + (ns & 3) * STG;
            cp16(sb + offA[0], aSrc + ns * 64);
            cp16(sb + offA[1], aSrc + ns * 64 + 8);
#pragma unroll
            for (int j = 0; j < 4; ++j)
                cp16(sb + OFF_B + offB[j], bSrc + ns * 64 + j * 8);
            cp_commit();
        }

        const uint32_t so = (kc & 3) * STG;
#pragma unroll
        for (int kq = 0; kq < 4; ++kq) {
            const uint32_t kk = (uint32_t)(kq << 5);
            uint32_t a0[4], a1[4], bf[4][4];
            ldmx4(a0, (aA0 + so) ^ kk);
            ldmx4(a1, (aA1 + so) ^ kk);
            ldmx4(bf[0], (aB0 + so) ^ kk);
            ldmx4(bf[1], (aB1 + so) ^ kk);
            ldmx4(bf[2], (aB2 + so) ^ kk);
            ldmx4(bf[3], (aB3 + so) ^ kk);
#pragma unroll
            for (int t = 0; t < 4; ++t) {
                mma16816(acc[0][t * 2],     a0, bf[t][0], bf[t][2]);
                mma16816(acc[0][t * 2 + 1], a0, bf[t][1], bf[t][3]);
                mma16816(acc[1][t * 2],     a1, bf[t][0], bf[t][2]);
                mma16816(acc[1][t * 2 + 1], a1, bf[t][1], bf[t][3]);
            }
        }
    }
    __syncthreads();

    // ---- epilogue: per-(ngroup,row) race-free slots, then combine ----
    const int gid = lane >> 2, t4 = lane & 3;
#pragma unroll
    for (int mt = 0; mt < 2; ++mt) {
        float s0 = 0.f, s1 = 0.f;
#pragma unroll
        for (int nt = 0; nt < 8; ++nt) {
            int c = nbase + nt * 8 + t4 * 2;
            float q0 = qs[c], q1 = qs[c + 1], v0 = Vs[c], v1 = Vs[c + 1];
            float* d = acc[mt][nt];
            s0 += tanh_fast(d[0] + q0) * v0 + tanh_fast(d[1] + q1) * v1;
            s1 += tanh_fast(d[2] + q0) * v0 + tanh_fast(d[3] + q1) * v1;
        }
        s0 += __shfl_xor_sync(0xffffffffu, s0, 1);
        s0 += __shfl_xor_sync(0xffffffffu, s0, 2);
        s1 += __shfl_xor_sync(0xffffffffu, s1, 1);
        s1 += __shfl_xor_sync(0xffffffffu, s1, 2);
        if (t4 == 0) {
            es4[nidx][mbase + mt * 16 + gid]     = s0;
            es4[nidx][mbase + mt * 16 + gid + 8] = s1;
        }
    }
    __syncthreads();
    if (tid < 128)
        g_ep[nc][b * S_ + row0 + tid] =
            es4[0][tid] + es4[1][tid] + es4[2][tid] + es4[3][tid];
}

// ---------------- K2: single-pass softmax (no max needed: |e| <= sum|V| < 87) --
__global__ __launch_bounds__(256) void stats_kernel(const int* __restrict__ lens,
                                                    float* __restrict__ out) {
    int b = blockIdx.x;
    int tid = threadIdx.x;
    int len = lens[b];
    __shared__ float red[256];

    out[b * H_ + tid] = 0.f;
    out[b * H_ + tid + 256] = 0.f;

    float sm = 0.f;
    for (int s = tid; s < S_; s += 256) {
        int i = b * S_ + s;
        float w = (s < len) ? __expf(g_ep[0][i] + g_ep[1][i]) : 0.f;
        g_energy[i] = w;
        sm += w;
    }
    red[tid] = sm;
    __syncthreads();
    for (int o = 128; o > 0; o >>= 1) {
        if (tid < o) red[tid] += red[tid + o];
        __syncthreads();
    }
    if (tid == 0) g_invden[b] = 1.0f / red[0];
}

// ---------------- K3: context = sum_s w[s] * enc_fp16[b,s,:] ----------------
__global__ __launch_bounds__(256) void context_kernel(const int* __restrict__ lens,
                                                      float* __restrict__ out) {
    const int b     = blockIdx.x >> 5;
    const int chunk = blockIdx.x & 31;
    const int row0  = chunk * 64;
    const int len   = lens[b];
    if (row0 >= len) return;

    __shared__ float ws[64];
    const int tid = threadIdx.x;
    if (tid < 64)
        ws[tid] = g_energy[b * S_ + row0 + tid] * g_invden[b];
    __syncthreads();

    const int smax = min(64, len - row0);
    const __half2* base = (const __half2*)(g_encF + ((size_t)b * S_ + row0) * H_) + tid;
    float c0 = 0.f, c1 = 0.f;
#pragma unroll 8
    for (int s = 0; s < smax; ++s) {
        float2 f = __half22float2(base[s * 256]);
        float w = ws[s];
        c0 += w * f.x;
        c1 += w * f.y;
    }
    atomicAdd(&out[b * H_ + tid * 2], c0);
    atomicAdd(&out[b * H_ + tid * 2 + 1], c1);
}

// ---------------- launch ----------------
extern "C" void kernel_launch(void* const* d_in, const int* in_sizes, int n_in,
                              void* d_out, int out_size) {
    const float* dec  = (const float*)d_in[0];
    const float* enc  = (const float*)d_in[1];
    const int*   lens = (const int*)d_in[2];
    const float* W1   = (const float*)d_in[3];
    const float* W2   = (const float*)d_in[4];
    const float* V    = (const float*)d_in[5];
    float* out = (float*)d_out;

    cudaFuncSetAttribute(energy_kernel,
                         cudaFuncAttributeMaxDynamicSharedMemorySize, DSMEM);

    prep_kernel<<<9280, 256>>>(enc, lens, W1, dec, W2);
    energy_kernel<<<B_ * 32, 512, DSMEM>>>(V, lens);
    stats_kernel<<<B_, 256>>>(lens, out);
    context_kernel<<<B_ * (S_ / 64), 256>>>(lens, out);
}

// round 16
// speedup vs baseline: 1.2337x; 1.0356x over previous
#include <cuda_runtime.h>
#include <cuda_fp16.h>
#include <cstdint>
#include <cstddef>

#define B_ 64
#define S_ 2048
#define H_ 512

// ---------------- scratch (no allocations allowed) ----------------
__device__ float g_q[B_ * H_];            // query projection [B,H]
__device__ float g_ep[2][B_ * S_];        // energy partials per n-half
__device__ float g_den[B_];               // sum of exp-weights per batch
__device__ __half g_w1tF[H_ * H_];        // W1^T fp16 [n][k]
__device__ __half g_encF[(size_t)B_ * S_ * H_];  // enc fp16

// ---------------- helpers ----------------
__device__ __forceinline__ uint32_t smem_u32(const void* p) {
    uint32_t a;
    asm("{ .reg .u64 t; cvta.to.shared.u64 t, %1; cvt.u32.u64 %0, t; }" : "=r"(a) : "l"(p));
    return a;
}
#define SW128(o) ((o) ^ (((o) >> 3) & 0x70))

__device__ __forceinline__ uint32_t cvtf2(float lo, float hi) {  // f16x2 {hi,lo}
    uint32_t r;
    asm("cvt.rn.f16x2.f32 %0, %1, %2;" : "=r"(r) : "f"(hi), "f"(lo));
    return r;
}
__device__ __forceinline__ float tanh_fast(float x) {
    float e = __expf(2.0f * x);
    return 1.0f - __fdividef(2.0f, e + 1.0f);
}
__device__ __forceinline__ void cp16(uint32_t dst, const void* src) {
    asm volatile("cp.async.cg.shared.global [%0], [%1], 16;" :: "r"(dst), "l"(src) : "memory");
}
__device__ __forceinline__ void cp_commit() {
    asm volatile("cp.async.commit_group;" ::: "memory");
}
__device__ __forceinline__ void cp_wait2() {
    asm volatile("cp.async.wait_group 2;" ::: "memory");
}
__device__ __forceinline__ void cp_wait1() {
    asm volatile("cp.async.wait_group 1;" ::: "memory");
}
__device__ __forceinline__ void cp_wait0() {
    asm volatile("cp.async.wait_group 0;" ::: "memory");
}
__device__ __forceinline__ void ldmx4(uint32_t* r, uint32_t addr) {
    asm volatile("ldmatrix.sync.aligned.m8n8.x4.shared.b16 {%0,%1,%2,%3}, [%4];"
                 : "=r"(r[0]), "=r"(r[1]), "=r"(r[2]), "=r"(r[3]) : "r"(addr));
}
__device__ __forceinline__ void mma16816(float* d, const uint32_t* a, uint32_t b0, uint32_t b1) {
    asm volatile(
        "mma.sync.aligned.m16n8k16.row.col.f32.f16.f16.f32 "
        "{%0,%1,%2,%3}, {%4,%5,%6,%7}, {%8,%9}, {%0,%1,%2,%3};"
        : "+f"(d[0]), "+f"(d[1]), "+f"(d[2]), "+f"(d[3])
        : "r"(a[0]), "r"(a[1]), "r"(a[2]), "r"(a[3]), "r"(b0), "r"(b1));
}

// ---------------- K0: fused prep (qproj | w1conv | encconv) ----------------
// Serial blocks (qproj) launch FIRST so they overlap the streaming encconv.
__global__ __launch_bounds__(256) void prep_kernel(const float* __restrict__ enc,
                                                   const int* __restrict__ lens,
                                                   const float* __restrict__ W1,
                                                   const float* __restrict__ dec,
                                                   const float* __restrict__ W2,
                                                   float* __restrict__ out) {
    const int blk = blockIdx.x;
    const int tid = threadIdx.x;

    if (blk < 64) {                         // ---- qproj + per-batch resets ----
        const int b = blk;
        __shared__ float xs[H_];
        xs[tid] = dec[b * H_ + tid];
        xs[tid + 256] = dec[b * H_ + tid + 256];
        if (tid == 0) g_den[b] = 0.f;
        out[b * H_ + tid] = 0.f;
        out[b * H_ + tid + 256] = 0.f;
        __syncthreads();
        float a0 = 0.f, a1 = 0.f;
#pragma unroll 8
        for (int h = 0; h < H_; ++h) {
            float x = xs[h];
            a0 += x * W2[(size_t)h * H_ + tid];
            a1 += x * W2[(size_t)h * H_ + tid + 256];
        }
        g_q[b * H_ + tid] = a0;
        g_q[b * H_ + tid + 256] = a1;
    } else if (blk < 1088) {                // ---- w1conv ----
        int idx = (blk - 64) * 256 + tid;   // idx = n*512 + k
        int n = idx >> 9, k = idx & 511;
        g_w1tF[idx] = __float2half(W1[(size_t)k * H_ + n]);
    } else {                                // ---- encconv (16 rows each) ----
        const int eb   = blk - 1088;
        const int b    = eb >> 7;
        const int row0 = (eb & 127) << 4;
        const int lim  = ((lens[b] + 127) >> 7) << 7;
        if (row0 >= lim) return;
        const size_t base = ((size_t)b * S_ + row0) * H_;
        const float4* src = (const float4*)(enc + base);
        uint2* dh = (uint2*)(g_encF + base);
        float4 v[8];
#pragma unroll
        for (int j = 0; j < 8; ++j) v[j] = src[tid + (j << 8)];
#pragma unroll
        for (int j = 0; j < 8; ++j)
            dh[tid + (j << 8)] = make_uint2(cvtf2(v[j].x, v[j].y),
                                            cvtf2(v[j].z, v[j].w));
    }
}

// ---------------- K1: fp16 mma.sync energy GEMM ----------------
// CTA: 128 rows x 256 cols, K=512 in 8 chunks of 64, 4-stage cp.async pipeline.
// 16 warps, warp grid 4M x 4N, warp tile 32x64. 1 CTA/SM (193KB smem).
#define STG    49152       // per-stage: A 16KB + B 32KB
#define OFF_B  16384
#define DSMEM  (1024 + 4 * STG)   // 197632

__global__ __launch_bounds__(512, 1) void energy_kernel(const float* __restrict__ Vv,
                                                        const int* __restrict__ lens) {
    // grid: b*32 + tile*2 + nc
    const int nc   = blockIdx.x & 1;
    const int tile = (blockIdx.x >> 1) & 15;
    const int b    = blockIdx.x >> 5;
    const int row0 = tile << 7;
    const int n0   = nc << 8;
    if (row0 >= lens[b]) return;

    extern __shared__ char dsm[];
    __shared__ float qs[256], Vs[256], es4[4][128];

    const int tid  = threadIdx.x;
    const int wid  = tid >> 5;
    const int lane = tid & 31;
    const int mbase = (wid & 3) << 5;   // 0..96
    const int nidx  = wid >> 2;         // 0..3
    const int nbase = nidx << 6;        // 0..192

    const uint32_t dynB = smem_u32(dsm);
    const uint32_t tb   = (dynB + 1023u) & ~1023u;

    if (tid < 256) {
        qs[tid] = g_q[b * H_ + n0 + tid];
        Vs[tid] = Vv[n0 + tid];
    }

    // cp.async slots: A: ra = tid>>2, qa = tid&3 (2x cp16)
    //                 B: rb2 = tid>>1, seg = tid&1 (4x cp16)
    const int ra = tid >> 2, qa = tid & 3;
    const int rb2 = tid >> 1, seg = tid & 1;
    const __half* aSrc = g_encF + ((size_t)b * S_ + row0 + ra) * H_ + qa * 16;
    const __half* bSrc = g_w1tF + ((size_t)(n0 + rb2)) * H_ + seg * 32;
    uint32_t offA[2], offB[4];
#pragma unroll
    for (int j = 0; j < 2; ++j)
        offA[j] = SW128((uint32_t)(ra * 128 + qa * 32 + j * 16));
#pragma unroll
    for (int j = 0; j < 4; ++j)
        offB[j] = SW128((uint32_t)(rb2 * 128 + seg * 64 + j * 16));

    // ldmatrix swizzled bases; kq*32 folds with XOR (bits 5..6), stage adds.
    const int rbl = (((lane & 15) >> 3) << 3) + (lane & 7);
    const int c16 = (lane >> 4) << 4;
    const uint32_t aA0 = tb + SW128((uint32_t)((mbase + rbl) * 128 + c16));
    const uint32_t aA1 = tb + SW128((uint32_t)((mbase + 16 + rbl) * 128 + c16));
    const uint32_t aB0 = tb + OFF_B + SW128((uint32_t)((nbase + rbl) * 128 + c16));
    const uint32_t aB1 = tb + OFF_B + SW128((uint32_t)((nbase + 16 + rbl) * 128 + c16));
    const uint32_t aB2 = tb + OFF_B + SW128((uint32_t)((nbase + 32 + rbl) * 128 + c16));
    const uint32_t aB3 = tb + OFF_B + SW128((uint32_t)((nbase + 48 + rbl) * 128 + c16));

    float acc[2][8][4];
#pragma unroll
    for (int i = 0; i < 2; ++i)
#pragma unroll
        for (int j = 0; j < 8; ++j)
#pragma unroll
            for (int q = 0; q < 4; ++q) acc[i][j][q] = 0.f;

    // prologue: stages 0,1,2
#pragma unroll
    for (int s = 0; s < 3; ++s) {
        const uint32_t sb = tb + s * STG;
        cp16(sb + offA[0], aSrc + s * 64);
        cp16(sb + offA[1], aSrc + s * 64 + 8);
#pragma unroll
        for (int j = 0; j < 4; ++j)
            cp16(sb + OFF_B + offB[j], bSrc + s * 64 + j * 8);
        cp_commit();
    }

#pragma unroll
    for (int kc = 0; kc < 8; ++kc) {
        if (kc <= 5) cp_wait2();
        else if (kc == 6) cp_wait1();
        else cp_wait0();
        __syncthreads();

        if (kc < 5) {
            const int ns = kc + 3;
            const uint32_t sb = tb + (ns & 3) * STG;
            cp16(sb + offA[0], aSrc + ns * 64);
            cp16(sb + offA[1], aSrc + ns * 64 + 8);
#pragma unroll
            for (int j = 0; j < 4; ++j)
                cp16(sb + OFF_B + offB[j], bSrc + ns * 64 + j * 8);
            cp_commit();
        }

        const uint32_t so = (kc & 3) * STG;
#pragma unroll
        for (int kq = 0; kq < 4; ++kq) {
            const uint32_t kk = (uint32_t)(kq << 5);
            uint32_t a0[4], a1[4], bf[4][4];
            ldmx4(a0, (aA0 + so) ^ kk);
            ldmx4(a1, (aA1 + so) ^ kk);
            ldmx4(bf[0], (aB0 + so) ^ kk);
            ldmx4(bf[1], (aB1 + so) ^ kk);
            ldmx4(bf[2], (aB2 + so) ^ kk);
            ldmx4(bf[3], (aB3 + so) ^ kk);
#pragma unroll
            for (int t = 0; t < 4; ++t) {
                mma16816(acc[0][t * 2],     a0, bf[t][0], bf[t][2]);
                mma16816(acc[0][t * 2 + 1], a0, bf[t][1], bf[t][3]);
                mma16816(acc[1][t * 2],     a1, bf[t][0], bf[t][2]);
                mma16816(acc[1][t * 2 + 1], a1, bf[t][1], bf[t][3]);
            }
        }
    }
    __syncthreads();

    // ---- epilogue: per-(ngroup,row) race-free slots, then combine ----
    const int gid = lane >> 2, t4 = lane & 3;
#pragma unroll
    for (int mt = 0; mt < 2; ++mt) {
        float s0 = 0.f, s1 = 0.f;
#pragma unroll
        for (int nt = 0; nt < 8; ++nt) {
            int c = nbase + nt * 8 + t4 * 2;
            float q0 = qs[c], q1 = qs[c + 1], v0 = Vs[c], v1 = Vs[c + 1];
            float* d = acc[mt][nt];
            s0 += tanh_fast(d[0] + q0) * v0 + tanh_fast(d[1] + q1) * v1;
            s1 += tanh_fast(d[2] + q0) * v0 + tanh_fast(d[3] + q1) * v1;
        }
        s0 += __shfl_xor_sync(0xffffffffu, s0, 1);
        s0 += __shfl_xor_sync(0xffffffffu, s0, 2);
        s1 += __shfl_xor_sync(0xffffffffu, s1, 1);
        s1 += __shfl_xor_sync(0xffffffffu, s1, 2);
        if (t4 == 0) {
            es4[nidx][mbase + mt * 16 + gid]     = s0;
            es4[nidx][mbase + mt * 16 + gid + 8] = s1;
        }
    }
    __syncthreads();
    if (tid < 128)
        g_ep[nc][b * S_ + row0 + tid] =
            es4[0][tid] + es4[1][tid] + es4[2][tid] + es4[3][tid];
}

// ---------------- K2: context (unnormalized) + per-batch weight sum ---------
// w = exp(e) computed inline (bounded: |e| <= sum|V| < 87, no max pass needed).
__global__ __launch_bounds__(256) void context_kernel(const int* __restrict__ lens,
                                                      float* __restrict__ out) {
    const int b     = blockIdx.x >> 5;
    const int chunk = blockIdx.x & 31;
    const int row0  = chunk * 64;
    const int len   = lens[b];
    if (row0 >= len) return;

    __shared__ float ws[64];
    const int tid = threadIdx.x;
    const int smax = min(64, len - row0);
    if (tid < 64) {
        int i = b * S_ + row0 + tid;
        ws[tid] = (tid < smax) ? __expf(g_ep[0][i] + g_ep[1][i]) : 0.f;
    }
    __syncthreads();

    // partial weight-sum for this chunk (warps 0,1 hold ws in lanes)
    if (tid < 64) {
        float w = ws[tid];
#pragma unroll
        for (int o = 16; o > 0; o >>= 1)
            w += __shfl_xor_sync(0xffffffffu, w, o);
        if ((tid & 31) == 0) atomicAdd(&g_den[b], w);
    }

    const __half2* base = (const __half2*)(g_encF + ((size_t)b * S_ + row0) * H_) + tid;
    float c0 = 0.f, c1 = 0.f;
#pragma unroll 8
    for (int s = 0; s < smax; ++s) {
        float2 f = __half22float2(base[s * 256]);
        float w = ws[s];
        c0 += w * f.x;
        c1 += w * f.y;
    }
    atomicAdd(&out[b * H_ + tid * 2], c0);
    atomicAdd(&out[b * H_ + tid * 2 + 1], c1);
}

// ---------------- K3: scale by 1/den ----------------
__global__ __launch_bounds__(512) void scale_kernel(float* __restrict__ out) {
    const int b = blockIdx.x;
    const float inv = 1.0f / g_den[b];
    out[b * H_ + threadIdx.x] *= inv;
}

// ---------------- launch ----------------
extern "C" void kernel_launch(void* const* d_in, const int* in_sizes, int n_in,
                              void* d_out, int out_size) {
    const float* dec  = (const float*)d_in[0];
    const float* enc  = (const float*)d_in[1];
    const int*   lens = (const int*)d_in[2];
    const float* W1   = (const float*)d_in[3];
    const float* W2   = (const float*)d_in[4];
    const float* V    = (const float*)d_in[5];
    float* out = (float*)d_out;

    cudaFuncSetAttribute(energy_kernel,
                         cudaFuncAttributeMaxDynamicSharedMemorySize, DSMEM);

    prep_kernel<<<9280, 256>>>(enc, lens, W1, dec, W2, out);
    energy_kernel<<<B_ * 32, 512, DSMEM>>>(V, lens);
    context_kernel<<<B_ * (S_ / 64), 256>>>(lens, out);
    scale_kernel<<<B_, 512>>>(out);
}

// round 17
// speedup vs baseline: 1.2494x; 1.0127x over previous
#include <cuda_runtime.h>
#include <cuda_fp16.h>
#include <cstdint>
#include <cstddef>

#define B_ 64
#define S_ 2048
#define H_ 512

// ---------------- scratch (no allocations allowed) ----------------
__device__ float g_q[B_ * H_];            // query projection [B,H]
__device__ float g_ep[2][B_ * S_];        // energy partials per n-half
__device__ float g_den[B_];               // sum of exp-weights per batch
__device__ __half g_w1tF[H_ * H_];        // W1^T fp16 [n][k]
__device__ __half g_encF[(size_t)B_ * S_ * H_];  // enc fp16

// ---------------- helpers ----------------
__device__ __forceinline__ uint32_t smem_u32(const void* p) {
    uint32_t a;
    asm("{ .reg .u64 t; cvta.to.shared.u64 t, %1; cvt.u32.u64 %0, t; }" : "=r"(a) : "l"(p));
    return a;
}
#define SW128(o) ((o) ^ (((o) >> 3) & 0x70))

__device__ __forceinline__ uint32_t cvtf2(float lo, float hi) {  // f16x2 {hi,lo}
    uint32_t r;
    asm("cvt.rn.f16x2.f32 %0, %1, %2;" : "=r"(r) : "f"(hi), "f"(lo));
    return r;
}
__device__ __forceinline__ float tanh_fast(float x) {
    float e = __expf(2.0f * x);
    return 1.0f - __fdividef(2.0f, e + 1.0f);
}
__device__ __forceinline__ void cp16(uint32_t dst, const void* src) {
    asm volatile("cp.async.cg.shared.global [%0], [%1], 16;" :: "r"(dst), "l"(src) : "memory");
}
__device__ __forceinline__ void cp_commit() {
    asm volatile("cp.async.commit_group;" ::: "memory");
}
__device__ __forceinline__ void cp_wait2() {
    asm volatile("cp.async.wait_group 2;" ::: "memory");
}
__device__ __forceinline__ void cp_wait1() {
    asm volatile("cp.async.wait_group 1;" ::: "memory");
}
__device__ __forceinline__ void cp_wait0() {
    asm volatile("cp.async.wait_group 0;" ::: "memory");
}
__device__ __forceinline__ void ldmx4(uint32_t* r, uint32_t addr) {
    asm volatile("ldmatrix.sync.aligned.m8n8.x4.shared.b16 {%0,%1,%2,%3}, [%4];"
                 : "=r"(r[0]), "=r"(r[1]), "=r"(r[2]), "=r"(r[3]) : "r"(addr));
}
__device__ __forceinline__ void mma16816(float* d, const uint32_t* a, uint32_t b0, uint32_t b1) {
    asm volatile(
        "mma.sync.aligned.m16n8k16.row.col.f32.f16.f16.f32 "
        "{%0,%1,%2,%3}, {%4,%5,%6,%7}, {%8,%9}, {%0,%1,%2,%3};"
        : "+f"(d[0]), "+f"(d[1]), "+f"(d[2]), "+f"(d[3])
        : "r"(a[0]), "r"(a[1]), "r"(a[2]), "r"(a[3]), "r"(b0), "r"(b1));
}

// ---------------- K0: fused prep (qproj | w1conv-transpose | encconv) -------
// blk [0,64):    qproj + per-batch resets (serial, launches first)
// blk [64,128):  W1 -> W1^T fp16, 64x64 smem tile transpose (coalesced both ways)
// blk [128,8320): enc -> fp16 (16 rows each, length-aware, uint4 stores)
__global__ __launch_bounds__(256) void prep_kernel(const float* __restrict__ enc,
                                                   const int* __restrict__ lens,
                                                   const float* __restrict__ W1,
                                                   const float* __restrict__ dec,
                                                   const float* __restrict__ W2,
                                                   float* __restrict__ out) {
    const int blk = blockIdx.x;
    const int tid = threadIdx.x;

    if (blk < 64) {                         // ---- qproj + per-batch resets ----
        const int b = blk;
        __shared__ float xs[H_];
        xs[tid] = dec[b * H_ + tid];
        xs[tid + 256] = dec[b * H_ + tid + 256];
        if (tid == 0) g_den[b] = 0.f;
        out[b * H_ + tid] = 0.f;
        out[b * H_ + tid + 256] = 0.f;
        __syncthreads();
        float a0 = 0.f, a1 = 0.f;
#pragma unroll 8
        for (int h = 0; h < H_; ++h) {
            float x = xs[h];
            a0 += x * W2[(size_t)h * H_ + tid];
            a1 += x * W2[(size_t)h * H_ + tid + 256];
        }
        g_q[b * H_ + tid] = a0;
        g_q[b * H_ + tid + 256] = a1;
    } else if (blk < 128) {                 // ---- w1conv: 64x64 tile transpose ----
        const int tIdx = blk - 64;          // 8x8 tiles
        const int k0 = (tIdx >> 3) << 6;
        const int n0 = (tIdx & 7) << 6;
        __shared__ __half sh[64][72];       // [n][k], 144B row stride (16B aligned)

        // read: 64 k-rows x 64 n-floats, coalesced float4
        {
            const int r = tid >> 2;          // k-row 0..63
            const int q = tid & 3;           // quarter
            const float4* src = (const float4*)(W1 + (size_t)(k0 + r) * H_ + n0) + q * 4;
#pragma unroll
            for (int j = 0; j < 4; ++j) {
                float4 v = src[j];
                int nOff = q * 16 + j * 4;
                sh[nOff + 0][r] = __float2half(v.x);
                sh[nOff + 1][r] = __float2half(v.y);
                sh[nOff + 2][r] = __float2half(v.z);
                sh[nOff + 3][r] = __float2half(v.w);
            }
        }
        __syncthreads();
        // write: 64 n-rows x 64 k-halfs (128B), coalesced uint4
        {
            const int rn = tid >> 2;         // n-row 0..63
            const int seg = tid & 3;         // 2x uint4 each
            uint4* dst = (uint4*)(g_w1tF + (size_t)(n0 + rn) * H_ + k0);
            const uint4* srow = (const uint4*)&sh[rn][0];
            dst[seg * 2]     = srow[seg * 2];
            dst[seg * 2 + 1] = srow[seg * 2 + 1];
        }
    } else {                                // ---- encconv (16 rows each) ----
        const int eb   = blk - 128;
        const int b    = eb >> 7;
        const int row0 = (eb & 127) << 4;
        const int lim  = ((lens[b] + 127) >> 7) << 7;
        if (row0 >= lim) return;
        const size_t base = ((size_t)b * S_ + row0) * H_;
        const float4* src = (const float4*)(enc + base);
        uint4* dst = (uint4*)(g_encF + base);
        // 1024 uint4 outputs; thread handles 4, each from 2 float4 loads.
        float4 v[8];
#pragma unroll
        for (int j = 0; j < 4; ++j) {
            int p = tid + (j << 8);
            v[j * 2]     = src[p * 2];
            v[j * 2 + 1] = src[p * 2 + 1];
        }
#pragma unroll
        for (int j = 0; j < 4; ++j) {
            float4 a = v[j * 2], bq = v[j * 2 + 1];
            dst[tid + (j << 8)] = make_uint4(cvtf2(a.x, a.y), cvtf2(a.z, a.w),
                                             cvtf2(bq.x, bq.y), cvtf2(bq.z, bq.w));
        }
    }
}

// ---------------- K1: fp16 mma.sync energy GEMM ----------------
// CTA: 128 rows x 256 cols, K=512 in 8 chunks of 64, 4-stage cp.async pipeline.
// 16 warps, warp grid 4M x 4N, warp tile 32x64. 1 CTA/SM (193KB smem).
#define STG    49152       // per-stage: A 16KB + B 32KB
#define OFF_B  16384
#define DSMEM  (1024 + 4 * STG)   // 197632

__global__ __launch_bounds__(512, 1) void energy_kernel(const float* __restrict__ Vv,
                                                        const int* __restrict__ lens) {
    // grid: b*32 + tile*2 + nc
    const int nc   = blockIdx.x & 1;
    const int tile = (blockIdx.x >> 1) & 15;
    const int b    = blockIdx.x >> 5;
    const int row0 = tile << 7;
    const int n0   = nc << 8;
    if (row0 >= lens[b]) return;

    extern __shared__ char dsm[];
    __shared__ float qs[256], Vs[256], es4[4][128];

    const int tid  = threadIdx.x;
    const int wid  = tid >> 5;
    const int lane = tid & 31;
    const int mbase = (wid & 3) << 5;   // 0..96
    const int nidx  = wid >> 2;         // 0..3
    const int nbase = nidx << 6;        // 0..192

    const uint32_t dynB = smem_u32(dsm);
    const uint32_t tb   = (dynB + 1023u) & ~1023u;

    if (tid < 256) {
        qs[tid] = g_q[b * H_ + n0 + tid];
        Vs[tid] = Vv[n0 + tid];
    }

    // cp.async slots: A: ra = tid>>2, qa = tid&3 (2x cp16)
    //                 B: rb2 = tid>>1, seg = tid&1 (4x cp16)
    const int ra = tid >> 2, qa = tid & 3;
    const int rb2 = tid >> 1, seg = tid & 1;
    const __half* aSrc = g_encF + ((size_t)b * S_ + row0 + ra) * H_ + qa * 16;
    const __half* bSrc = g_w1tF + ((size_t)(n0 + rb2)) * H_ + seg * 32;
    uint32_t offA[2], offB[4];
#pragma unroll
    for (int j = 0; j < 2; ++j)
        offA[j] = SW128((uint32_t)(ra * 128 + qa * 32 + j * 16));
#pragma unroll
    for (int j = 0; j < 4; ++j)
        offB[j] = SW128((uint32_t)(rb2 * 128 + seg * 64 + j * 16));

    // ldmatrix swizzled bases; kq*32 folds with XOR (bits 5..6), stage adds.
    const int rbl = (((lane & 15) >> 3) << 3) + (lane & 7);
    const int c16 = (lane >> 4) << 4;
    const uint32_t aA0 = tb + SW128((uint32_t)((mbase + rbl) * 128 + c16));
    const uint32_t aA1 = tb + SW128((uint32_t)((mbase + 16 + rbl) * 128 + c16));
    const uint32_t aB0 = tb + OFF_B + SW128((uint32_t)((nbase + rbl) * 128 + c16));
    const uint32_t aB1 = tb + OFF_B + SW128((uint32_t)((nbase + 16 + rbl) * 128 + c16));
    const uint32_t aB2 = tb + OFF_B + SW128((uint32_t)((nbase + 32 + rbl) * 128 + c16));
    const uint32_t aB3 = tb + OFF_B + SW128((uint32_t)((nbase + 48 + rbl) * 128 + c16));

    float acc[2][8][4];
#pragma unroll
    for (int i = 0; i < 2; ++i)
#pragma unroll
        for (int j = 0; j < 8; ++j)
#pragma unroll
            for (int q = 0; q < 4; ++q) acc[i][j][q] = 0.f;

    // prologue: stages 0,1,2
#pragma unroll
    for (int s = 0; s < 3; ++s) {
        const uint32_t sb = tb + s * STG;
        cp16(sb + offA[0], aSrc + s * 64);
        cp16(sb + offA[1], aSrc + s * 64 + 8);
#pragma unroll
        for (int j = 0; j < 4; ++j)
            cp16(sb + OFF_B + offB[j], bSrc + s * 64 + j * 8);
        cp_commit();
    }

#pragma unroll
    for (int kc = 0; kc < 8; ++kc) {
        if (kc <= 5) cp_wait2();
        else if (kc == 6) cp_wait1();
        else cp_wait0();
        __syncthreads();

        if (kc < 5) {
            const int ns = kc + 3;
            const uint32_t sb = tb + (ns & 3) * STG;
            cp16(sb + offA[0], aSrc + ns * 64);
            cp16(sb + offA[1], aSrc + ns * 64 + 8);
#pragma unroll
            for (int j = 0; j < 4; ++j)
                cp16(sb + OFF_B + offB[j], bSrc + ns * 64 + j * 8);
            cp_commit();
        }

        const uint32_t so = (kc & 3) * STG;
#pragma unroll
        for (int kq = 0; kq < 4; ++kq) {
            const uint32_t kk = (uint32_t)(kq << 5);
            uint32_t a0[4], a1[4], bf[4][4];
            ldmx4(a0, (aA0 + so) ^ kk);
            ldmx4(a1, (aA1 + so) ^ kk);
            ldmx4(bf[0], (aB0 + so) ^ kk);
            ldmx4(bf[1], (aB1 + so) ^ kk);
            ldmx4(bf[2], (aB2 + so) ^ kk);
            ldmx4(bf[3], (aB3 + so) ^ kk);
#pragma unroll
            for (int t = 0; t < 4; ++t) {
                mma16816(acc[0][t * 2],     a0, bf[t][0], bf[t][2]);
                mma16816(acc[0][t * 2 + 1], a0, bf[t][1], bf[t][3]);
                mma16816(acc[1][t * 2],     a1, bf[t][0], bf[t][2]);
                mma16816(acc[1][t * 2 + 1], a1, bf[t][1], bf[t][3]);
            }
        }
    }
    __syncthreads();

    // ---- epilogue: per-(ngroup,row) race-free slots, then combine ----
    const int gid = lane >> 2, t4 = lane & 3;
#pragma unroll
    for (int mt = 0; mt < 2; ++mt) {
        float s0 = 0.f, s1 = 0.f;
#pragma unroll
        for (int nt = 0; nt < 8; ++nt) {
            int c = nbase + nt * 8 + t4 * 2;
            float q0 = qs[c], q1 = qs[c + 1], v0 = Vs[c], v1 = Vs[c + 1];
            float* d = acc[mt][nt];
            s0 += tanh_fast(d[0] + q0) * v0 + tanh_fast(d[1] + q1) * v1;
            s1 += tanh_fast(d[2] + q0) * v0 + tanh_fast(d[3] + q1) * v1;
        }
        s0 += __shfl_xor_sync(0xffffffffu, s0, 1);
        s0 += __shfl_xor_sync(0xffffffffu, s0, 2);
        s1 += __shfl_xor_sync(0xffffffffu, s1, 1);
        s1 += __shfl_xor_sync(0xffffffffu, s1, 2);
        if (t4 == 0) {
            es4[nidx][mbase + mt * 16 + gid]     = s0;
            es4[nidx][mbase + mt * 16 + gid + 8] = s1;
        }
    }
    __syncthreads();
    if (tid < 128)
        g_ep[nc][b * S_ + row0 + tid] =
            es4[0][tid] + es4[1][tid] + es4[2][tid] + es4[3][tid];
}

// ---------------- K2: context (unnormalized) + per-batch weight sum ---------
__global__ __launch_bounds__(256) void context_kernel(const int* __restrict__ lens,
                                                      float* __restrict__ out) {
    const int b     = blockIdx.x >> 5;
    const int chunk = blockIdx.x & 31;
    const int row0  = chunk * 64;
    const int len   = lens[b];
    if (row0 >= len) return;

    __shared__ float ws[64];
    const int tid = threadIdx.x;
    const int smax = min(64, len - row0);
    if (tid < 64) {
        int i = b * S_ + row0 + tid;
        ws[tid] = (tid < smax) ? __expf(g_ep[0][i] + g_ep[1][i]) : 0.f;
    }
    __syncthreads();

    if (tid < 64) {
        float w = ws[tid];
#pragma unroll
        for (int o = 16; o > 0; o >>= 1)
            w += __shfl_xor_sync(0xffffffffu, w, o);
        if ((tid & 31) == 0) atomicAdd(&g_den[b], w);
    }

    const __half2* base = (const __half2*)(g_encF + ((size_t)b * S_ + row0) * H_) + tid;
    float c0 = 0.f, c1 = 0.f;
#pragma unroll 8
    for (int s = 0; s < smax; ++s) {
        float2 f = __half22float2(base[s * 256]);
        float w = ws[s];
        c0 += w * f.x;
        c1 += w * f.y;
    }
    atomicAdd(&out[b * H_ + tid * 2], c0);
    atomicAdd(&out[b * H_ + tid * 2 + 1], c1);
}

// ---------------- K3: scale by 1/den ----------------
__global__ __launch_bounds__(512) void scale_kernel(float* __restrict__ out) {
    const int b = blockIdx.x;
    const float inv = 1.0f / g_den[b];
    out[b * H_ + threadIdx.x] *= inv;
}

// ---------------- launch ----------------
extern "C" void kernel_launch(void* const* d_in, const int* in_sizes, int n_in,
                              void* d_out, int out_size) {
    const float* dec  = (const float*)d_in[0];
    const float* enc  = (const float*)d_in[1];
    const int*   lens = (const int*)d_in[2];
    const float* W1   = (const float*)d_in[3];
    const float* W2   = (const float*)d_in[4];
    const float* V    = (const float*)d_in[5];
    float* out = (float*)d_out;

    cudaFuncSetAttribute(energy_kernel,
                         cudaFuncAttributeMaxDynamicSharedMemorySize, DSMEM);

    prep_kernel<<<8320, 256>>>(enc, lens, W1, dec, W2, out);
    energy_kernel<<<B_ * 32, 512, DSMEM>>>(V, lens);
    context_kernel<<<B_ * (S_ / 64), 256>>>(lens, out);
    scale_kernel<<<B_, 512>>>(out);
}